// round 9
// baseline (speedup 1.0000x reference)
#include <cuda_runtime.h>
#include <cuda_fp16.h>
#include <cstdint>

// Problem constants
#define BATCH 16384
#define NLOC  12
#define FDIM  512
#define HDIM  256

// ---------------- scratch (device globals; no runtime allocation) ----------------
__device__ __half g_th  [BATCH * FDIM];     // gf @ M0 + c0  (fp16)
__device__ __half g_resh[BATCH * FDIM];     // lf_mean + b_dr (fp16)
__device__ __half g_gfh [BATCH * FDIM];     // gf as fp16
__device__ __half g_uh  [BATCH * FDIM];     // softmax-weighted local rows (fp16)
__device__ __half g_M0h [FDIM * FDIM];      // (Wq@Wk^T)^T  [N=512, K=512] fp16
__device__ __half g_MMh [FDIM * 2 * FDIM];  // [(Wv@WfTop)^T | S*(Wv@WfBot)^T] fp16
__device__ __half g_WfTh[FDIM * FDIM];      // Wf^T (fp16, for prep GEMMs)
__device__ __half g_Wqh [FDIM * HDIM];
__device__ __half g_Wkh [FDIM * HDIM];
__device__ __half g_Wvh [FDIM * HDIM];
__device__ float  g_c0  [FDIM];
__device__ float  g_c   [FDIM];
__device__ float  g_S   [1];

// ---------------- PTX helpers ----------------
__device__ __forceinline__ void cp_async16(void* smem, const void* gmem) {
    unsigned s = (unsigned)__cvta_generic_to_shared(smem);
    asm volatile("cp.async.cg.shared.global [%0], [%1], 16;\n" :: "r"(s), "l"(gmem));
}
__device__ __forceinline__ void cp_commit() { asm volatile("cp.async.commit_group;\n"); }
__device__ __forceinline__ void cp_wait2() { asm volatile("cp.async.wait_group 2;\n"); }

__device__ __forceinline__ void mma_f16(float c[4], const uint32_t a[4], const uint32_t b[2]) {
    asm volatile(
        "mma.sync.aligned.m16n8k16.row.col.f32.f16.f16.f32 "
        "{%0,%1,%2,%3}, {%4,%5,%6,%7}, {%8,%9}, {%0,%1,%2,%3};\n"
        : "+f"(c[0]), "+f"(c[1]), "+f"(c[2]), "+f"(c[3])
        : "r"(a[0]), "r"(a[1]), "r"(a[2]), "r"(a[3]), "r"(b[0]), "r"(b[1]));
}
__device__ __forceinline__ void ldsm4(uint32_t& r0, uint32_t& r1, uint32_t& r2, uint32_t& r3,
                                      uint32_t addr) {
    asm volatile("ldmatrix.sync.aligned.m8n8.x4.shared.b16 {%0,%1,%2,%3}, [%4];"
                 : "=r"(r0), "=r"(r1), "=r"(r2), "=r"(r3) : "r"(addr));
}

#define HG_STAGE_H 10240          // halves per stage (A 5120 then B 5120)

// ================= fp16 tensor-core GEMM, 4-stage cp.async pipeline ============
// C[M,512] = A[M,K] @ Bt^T + cvec; block tile 128x128, BK=32, 256 thr (8 warps 32m x 64n).
// A half [*,512] row-major; SPLIT: kt >= KT/2 reads A1. Bt half [N,K] row-major.
// OUTH: C half, no res. FINAL: C = relu(D + cvec) + res_h + add2 (fp32 out).
template<int KT, bool SPLIT, bool FINAL, bool OUTH>
__global__ void __launch_bounds__(256, 2) hgemm(
    const __half* __restrict__ A0, const __half* __restrict__ A1,
    const __half* __restrict__ Bt, int ldb,
    const float* __restrict__ cvec, const __half* __restrict__ resh,
    const float* __restrict__ add2,
    void* __restrict__ Cout)
{
    extern __shared__ __half sm[];

    const int tid = threadIdx.x;
    const int wid = tid >> 5, lane = tid & 31;
    const int bm = blockIdx.y * 128, bn = blockIdx.x * 128;
    const int wm = (wid & 3) * 32, wn = (wid >> 2) * 64;
    const int g = lane >> 2, tq = lane & 3;

    float acc[2][8][4];
    #pragma unroll
    for (int mi = 0; mi < 2; mi++)
        #pragma unroll
        for (int ni = 0; ni < 8; ni++)
            #pragma unroll
            for (int i = 0; i < 4; i++) acc[mi][ni][i] = 0.f;

    const int q = lane >> 3, r8 = lane & 7;
    const int qRow = (q & 1) * 8 + r8;
    const int qCol = (q >> 1) * 8;
    const uint32_t smBase = (uint32_t)__cvta_generic_to_shared(&sm[0]);
    const uint32_t aLane = ((wm + qRow) * 40 + qCol) * 2;
    const uint32_t bLane = ((wn + qRow) * 40 + qCol) * 2 + 5120 * 2;

    const int row0 = tid >> 2, c16 = tid & 3;

    auto load_tile = [&](int kt, int st) {
        const __half* Ag = A0;
        int ktA = kt;
        if (SPLIT && kt >= KT / 2) { Ag = A1; ktA = kt - KT / 2; }
        __half* As = sm + st * HG_STAGE_H;
        __half* Bs = As + 5120;
        #pragma unroll
        for (int i = 0; i < 2; i++) {
            int row = row0 + i * 64;
            cp_async16(&As[row * 40 + c16 * 8],
                       Ag + (size_t)(bm + row) * 512 + ktA * 32 + c16 * 8);
            cp_async16(&Bs[row * 40 + c16 * 8],
                       Bt + (size_t)(bn + row) * ldb + kt * 32 + c16 * 8);
        }
    };

    load_tile(0, 0); cp_commit();
    load_tile(1, 1); cp_commit();
    load_tile(2, 2); cp_commit();

    for (int kt = 0; kt < KT; ++kt) {
        const int st = kt & 3;
        cp_wait2();
        __syncthreads();
        if (kt + 3 < KT) load_tile(kt + 3, (kt + 3) & 3);
        cp_commit();

        const uint32_t aB = smBase + st * (HG_STAGE_H * 2) + aLane;
        const uint32_t bB = smBase + st * (HG_STAGE_H * 2) + bLane;
        #pragma unroll
        for (int ks = 0; ks < 32; ks += 16) {
            uint32_t aF[2][4], bF[8][2];
            #pragma unroll
            for (int mi = 0; mi < 2; mi++)
                ldsm4(aF[mi][0], aF[mi][1], aF[mi][2], aF[mi][3],
                      aB + (mi * 16 * 40 + ks) * 2);
            #pragma unroll
            for (int nb = 0; nb < 4; nb++) {
                uint32_t t0, t1, t2, t3;
                ldsm4(t0, t1, t2, t3, bB + (nb * 16 * 40 + ks) * 2);
                bF[2 * nb][0] = t0; bF[2 * nb + 1][0] = t1;
                bF[2 * nb][1] = t2; bF[2 * nb + 1][1] = t3;
            }
            #pragma unroll
            for (int mi = 0; mi < 2; mi++)
                #pragma unroll
                for (int ni = 0; ni < 8; ni++)
                    mma_f16(acc[mi][ni], aF[mi], bF[ni]);
        }
        __syncthreads();
    }

    #pragma unroll
    for (int mi = 0; mi < 2; mi++)
        #pragma unroll
        for (int ni = 0; ni < 8; ni++) {
            int row = bm + wm + mi * 16 + g;
            int col = bn + wn + ni * 8 + 2 * tq;
            float b0 = cvec[col], b1 = cvec[col + 1];
            float v0 = acc[mi][ni][0] + b0, v1 = acc[mi][ni][1] + b1;
            float v2 = acc[mi][ni][2] + b0, v3 = acc[mi][ni][3] + b1;
            size_t o0 = (size_t)row * 512 + col;
            size_t o1 = (size_t)(row + 8) * 512 + col;
            if (OUTH) {
                __half* Ch = (__half*)Cout;
                *(__half2*)(Ch + o0) = __floats2half2_rn(v0, v1);
                *(__half2*)(Ch + o1) = __floats2half2_rn(v2, v3);
            } else {
                float* Cf = (float*)Cout;
                if (FINAL) {
                    const float2 r0 = __half22float2(*(const __half2*)(resh + o0));
                    const float2 r1 = __half22float2(*(const __half2*)(resh + o1));
                    const float2 g0 = *(const float2*)(add2 + o0);
                    const float2 g1 = *(const float2*)(add2 + o1);
                    v0 = fmaxf(v0, 0.f) + r0.x + g0.x;
                    v1 = fmaxf(v1, 0.f) + r0.y + g0.y;
                    v2 = fmaxf(v2, 0.f) + r1.x + g1.x;
                    v3 = fmaxf(v3, 0.f) + r1.y + g1.y;
                }
                *(float2*)(Cf + o0) = make_float2(v0, v1);
                *(float2*)(Cf + o1) = make_float2(v2, v3);
            }
        }
}

// ================= prep GEMMs: fp16 pipelined, all three products in one launch
// grid (4, 4, 3), 128x128 tiles, K=256 (KT=8).
__global__ void __launch_bounds__(256, 2) prep_hgemm(
    const __half* __restrict__ Wk_h, const __half* __restrict__ Wq_h,
    const __half* __restrict__ WfTh, const __half* __restrict__ Wv_h,
    const float* __restrict__ Sptr,
    __half* __restrict__ M0h, __half* __restrict__ MMh)
{
    extern __shared__ __half sm[];
    constexpr int KT = 8;

    const int z = blockIdx.z;
    const __half *A, *Bt;
    __half* C;
    int lda, ldc;
    float alpha = 1.f;
    if (z == 0)      { A = Wk_h;        lda = 256; Bt = Wq_h; C = M0h;       ldc = 512;  }
    else if (z == 1) { A = WfTh;        lda = 512; Bt = Wv_h; C = MMh;       ldc = 1024; }
    else             { A = WfTh + 256;  lda = 512; Bt = Wv_h; C = MMh + 512; ldc = 1024;
                       alpha = Sptr[0]; }

    const int tid = threadIdx.x;
    const int wid = tid >> 5, lane = tid & 31;
    const int bm = blockIdx.y * 128, bn = blockIdx.x * 128;
    const int wm = (wid & 3) * 32, wn = (wid >> 2) * 64;
    const int g = lane >> 2, tq = lane & 3;

    float acc[2][8][4];
    #pragma unroll
    for (int mi = 0; mi < 2; mi++)
        #pragma unroll
        for (int ni = 0; ni < 8; ni++)
            #pragma unroll
            for (int i = 0; i < 4; i++) acc[mi][ni][i] = 0.f;

    const int q = lane >> 3, r8 = lane & 7;
    const int qRow = (q & 1) * 8 + r8;
    const int qCol = (q >> 1) * 8;
    const uint32_t smBase = (uint32_t)__cvta_generic_to_shared(&sm[0]);
    const uint32_t aLane = ((wm + qRow) * 40 + qCol) * 2;
    const uint32_t bLane = ((wn + qRow) * 40 + qCol) * 2 + 5120 * 2;

    const int row0 = tid >> 2, c16 = tid & 3;

    auto load_tile = [&](int kt, int st) {
        __half* As = sm + st * HG_STAGE_H;
        __half* Bs = As + 5120;
        #pragma unroll
        for (int i = 0; i < 2; i++) {
            int row = row0 + i * 64;
            cp_async16(&As[row * 40 + c16 * 8],
                       A + (size_t)(bm + row) * lda + kt * 32 + c16 * 8);
            cp_async16(&Bs[row * 40 + c16 * 8],
                       Bt + (size_t)(bn + row) * 256 + kt * 32 + c16 * 8);
        }
    };

    load_tile(0, 0); cp_commit();
    load_tile(1, 1); cp_commit();
    load_tile(2, 2); cp_commit();

    for (int kt = 0; kt < KT; ++kt) {
        const int st = kt & 3;
        cp_wait2();
        __syncthreads();
        if (kt + 3 < KT) load_tile(kt + 3, (kt + 3) & 3);
        cp_commit();

        const uint32_t aB = smBase + st * (HG_STAGE_H * 2) + aLane;
        const uint32_t bB = smBase + st * (HG_STAGE_H * 2) + bLane;
        #pragma unroll
        for (int ks = 0; ks < 32; ks += 16) {
            uint32_t aF[2][4], bF[8][2];
            #pragma unroll
            for (int mi = 0; mi < 2; mi++)
                ldsm4(aF[mi][0], aF[mi][1], aF[mi][2], aF[mi][3],
                      aB + (mi * 16 * 40 + ks) * 2);
            #pragma unroll
            for (int nb = 0; nb < 4; nb++) {
                uint32_t t0, t1, t2, t3;
                ldsm4(t0, t1, t2, t3, bB + (nb * 16 * 40 + ks) * 2);
                bF[2 * nb][0] = t0; bF[2 * nb + 1][0] = t1;
                bF[2 * nb][1] = t2; bF[2 * nb + 1][1] = t3;
            }
            #pragma unroll
            for (int mi = 0; mi < 2; mi++)
                #pragma unroll
                for (int ni = 0; ni < 8; ni++)
                    mma_f16(acc[mi][ni], aF[mi], bF[ni]);
        }
        __syncthreads();
    }

    #pragma unroll
    for (int mi = 0; mi < 2; mi++)
        #pragma unroll
        for (int ni = 0; ni < 8; ni++) {
            int row = bm + wm + mi * 16 + g;
            int col = bn + wn + ni * 8 + 2 * tq;
            size_t o0 = (size_t)row * ldc + col;
            size_t o1 = (size_t)(row + 8) * ldc + col;
            *(__half2*)(C + o0) = __floats2half2_rn(acc[mi][ni][0] * alpha,
                                                    acc[mi][ni][1] * alpha);
            *(__half2*)(C + o1) = __floats2half2_rn(acc[mi][ni][2] * alpha,
                                                    acc[mi][ni][3] * alpha);
        }
}

// ================= prep_misc: ALL small prep work in one launch ================
// blockIdx.x ranges (256 threads each):
//   [0, 8192)      : gf -> gfh (fp16), 1 float4 / thread
//   [8192, 8576)   : Wq/Wk/Wv -> fp16 (128 blocks each)
//   [8576, 8832)   : Wf transpose -> WfTh (fp16), 32x32 tiles (16x16 grid)
//   [8832, 8834)   : c0, c, S (thread-per-f, 512 threads total)
__global__ void __launch_bounds__(256) prep_misc(
    const float* __restrict__ gf, const float* __restrict__ Wq,
    const float* __restrict__ Wk, const float* __restrict__ Wv,
    const float* __restrict__ Wf,
    const float* __restrict__ wdr, const float* __restrict__ bdrp,
    const float* __restrict__ bq, const float* __restrict__ bv,
    const float* __restrict__ bfv,
    __half* __restrict__ gfh, __half* __restrict__ Wqh,
    __half* __restrict__ Wkh, __half* __restrict__ Wvh,
    __half* __restrict__ WfTh,
    float* __restrict__ c0, float* __restrict__ c, float* __restrict__ Sout)
{
    __shared__ float tileS[32][33];
    const int tid = threadIdx.x;
    int bx = blockIdx.x;

    if (bx < 8192) {                       // gf convert
        int i = bx * 256 + tid;
        float4 v = ((const float4*)gf)[i];
        __half2 h0 = __floats2half2_rn(v.x, v.y);
        __half2 h1 = __floats2half2_rn(v.z, v.w);
        uint2 pk; pk.x = *(uint32_t*)&h0; pk.y = *(uint32_t*)&h1;
        ((uint2*)gfh)[i] = pk;
        return;
    }
    bx -= 8192;
    if (bx < 384) {                        // W q/k/v convert
        const float4* in; uint2* out;
        int sel = bx >> 7, sub = bx & 127;
        if (sel == 0)      { in = (const float4*)Wq; out = (uint2*)Wqh; }
        else if (sel == 1) { in = (const float4*)Wk; out = (uint2*)Wkh; }
        else               { in = (const float4*)Wv; out = (uint2*)Wvh; }
        int i = sub * 256 + tid;           // 128*256 = 32768 = 512*256/4
        float4 v = in[i];
        __half2 h0 = __floats2half2_rn(v.x, v.y);
        __half2 h1 = __floats2half2_rn(v.z, v.w);
        uint2 pk; pk.x = *(uint32_t*)&h0; pk.y = *(uint32_t*)&h1;
        out[i] = pk;
        return;
    }
    bx -= 384;
    if (bx < 256) {                        // Wf transpose -> fp16
        const int bxx = (bx & 15) * 32, byy = (bx >> 4) * 32;
        const int tx = tid & 31, ty = tid >> 5;
        #pragma unroll
        for (int i = 0; i < 32; i += 8)
            tileS[ty + i][tx] = Wf[(size_t)(byy + ty + i) * FDIM + bxx + tx];
        __syncthreads();
        #pragma unroll
        for (int i = 0; i < 32; i += 8)
            WfTh[(size_t)(bxx + ty + i) * FDIM + byy + tx] =
                __float2half(tileS[tx][ty + i]);
        return;
    }
    bx -= 256;
    {                                      // c0, c, S  (f = bx*256 + tid)
        const int f = bx * 256 + tid;
        float S = 0.f;
        #pragma unroll
        for (int k = 0; k < NLOC; k++) S += wdr[k];
        const float bd = bdrp[0];
        if (f == 0) Sout[0] = S;

        float a0 = 0.f;
        #pragma unroll 4
        for (int h = 0; h < HDIM; h++) a0 = fmaf(bq[h], Wk[f * HDIM + h], a0);
        c0[f] = a0;

        float a1 = bfv[f];
        #pragma unroll 4
        for (int h = 0; h < HDIM; h++) {
            const float bvh = bv[h];
            a1 = fmaf(bvh, Wf[(size_t)h * FDIM + f], a1);
            a1 = fmaf(fmaf(S, bvh, bd), Wf[(size_t)(HDIM + h) * FDIM + f], a1);
        }
        c[f] = a1;
    }
}

// ================= fused per-row kernel (t fp16, res out fp16) =================
__global__ void __launch_bounds__(128) row_fused_kernel(
    const float4* __restrict__ local, const uint2* __restrict__ t_h,
    const float* __restrict__ wdr, const float* __restrict__ bdrp,
    uint2* __restrict__ u_h, uint2* __restrict__ res_h)
{
    const int b = blockIdx.x, j = threadIdx.x;
    __shared__ float s_wdr[12], s_red[4][12], s_a2[12], s_bdr;
    if (j < 12) s_wdr[j] = wdr[j];
    if (j == 0) s_bdr = bdrp[0];

    const uint2 tp = t_h[b * 128 + j];
    const float2 t0 = __half22float2(*(const __half2*)&tp.x);
    const float2 t1 = __half22float2(*(const __half2*)&tp.y);
    const float4 tv = make_float4(t0.x, t0.y, t1.x, t1.y);

    float4 lf[12];
    float p[12];
    #pragma unroll
    for (int k = 0; k < 12; k++) {
        lf[k] = local[(size_t)(b * 12 + k) * 128 + j];
        p[k] = lf[k].x * tv.x + lf[k].y * tv.y + lf[k].z * tv.z + lf[k].w * tv.w;
    }
    #pragma unroll
    for (int off = 16; off > 0; off >>= 1)
        #pragma unroll
        for (int k = 0; k < 12; k++)
            p[k] += __shfl_xor_sync(0xffffffffu, p[k], off);
    if ((j & 31) == 0) {
        #pragma unroll
        for (int k = 0; k < 12; k++) s_red[j >> 5][k] = p[k];
    }
    __syncthreads();
    if (j == 0) {
        float s2[12], mx = -1e30f;
        #pragma unroll
        for (int k = 0; k < 12; k++) {
            s2[k] = (s_red[0][k] + s_red[1][k] + s_red[2][k] + s_red[3][k]) * 0.0625f;
            mx = fmaxf(mx, s2[k]);
        }
        float sum = 0.f;
        #pragma unroll
        for (int k = 0; k < 12; k++) { s2[k] = __expf(s2[k] - mx); sum += s2[k]; }
        const float inv = 1.f / sum;
        #pragma unroll
        for (int k = 0; k < 12; k++) s_a2[k] = s2[k] * inv;
    }
    __syncthreads();

    const float bdr = s_bdr;
    float4 uu = make_float4(0.f, 0.f, 0.f, 0.f);
    float4 rr = make_float4(bdr, bdr, bdr, bdr);
    #pragma unroll
    for (int k = 0; k < 12; k++) {
        const float a = s_a2[k], w = s_wdr[k];
        uu.x = fmaf(a, lf[k].x, uu.x); uu.y = fmaf(a, lf[k].y, uu.y);
        uu.z = fmaf(a, lf[k].z, uu.z); uu.w = fmaf(a, lf[k].w, uu.w);
        rr.x = fmaf(w, lf[k].x, rr.x); rr.y = fmaf(w, lf[k].y, rr.y);
        rr.z = fmaf(w, lf[k].z, rr.z); rr.w = fmaf(w, lf[k].w, rr.w);
    }

    __half2 ha = __floats2half2_rn(uu.x, uu.y);
    __half2 hb = __floats2half2_rn(uu.z, uu.w);
    uint2 pk;
    pk.x = *(uint32_t*)&ha;
    pk.y = *(uint32_t*)&hb;
    u_h[b * 128 + j] = pk;

    __half2 ra = __floats2half2_rn(rr.x, rr.y);
    __half2 rb = __floats2half2_rn(rr.z, rr.w);
    uint2 rk;
    rk.x = *(uint32_t*)&ra;
    rk.y = *(uint32_t*)&rb;
    res_h[b * 128 + j] = rk;
}

// ================= launch =================
static constexpr int HG_SMEM = 4 * HG_STAGE_H * 2;        // 81920 B

extern "C" void kernel_launch(void* const* d_in, const int* in_sizes, int n_in,
                              void* d_out, int out_size) {
    const float* gf  = (const float*)d_in[0];   // [B, F]
    const float* lf  = (const float*)d_in[1];   // [B, 12, F]
    const float* Wq  = (const float*)d_in[2];   // [F, H]
    const float* bq  = (const float*)d_in[3];   // [H]
    const float* Wk  = (const float*)d_in[4];   // [F, H]  (bk softmax-invariant: dropped)
    const float* Wv  = (const float*)d_in[6];   // [F, H]
    const float* bv  = (const float*)d_in[7];   // [H]
    const float* wdr = (const float*)d_in[8];   // [12]
    const float* bdr = (const float*)d_in[9];   // scalar
    const float* Wf  = (const float*)d_in[10];  // [2H, F]
    const float* bfv = (const float*)d_in[11];  // [F]
    float* out = (float*)d_out;

    float *c0, *c, *S;
    __half *th, *resh, *gfh, *uh, *M0h, *MMh, *WfTh, *Wqh, *Wkh, *Wvh;
    cudaGetSymbolAddress((void**)&th,   g_th);
    cudaGetSymbolAddress((void**)&resh, g_resh);
    cudaGetSymbolAddress((void**)&gfh,  g_gfh);
    cudaGetSymbolAddress((void**)&uh,   g_uh);
    cudaGetSymbolAddress((void**)&M0h,  g_M0h);
    cudaGetSymbolAddress((void**)&MMh,  g_MMh);
    cudaGetSymbolAddress((void**)&WfTh, g_WfTh);
    cudaGetSymbolAddress((void**)&Wqh,  g_Wqh);
    cudaGetSymbolAddress((void**)&Wkh,  g_Wkh);
    cudaGetSymbolAddress((void**)&Wvh,  g_Wvh);
    cudaGetSymbolAddress((void**)&c0,   g_c0);
    cudaGetSymbolAddress((void**)&c,    g_c);
    cudaGetSymbolAddress((void**)&S,    g_S);

    cudaFuncSetAttribute(hgemm<16, false, false, true>,
                         cudaFuncAttributeMaxDynamicSharedMemorySize, HG_SMEM);
    cudaFuncSetAttribute(hgemm<32, true, true, false>,
                         cudaFuncAttributeMaxDynamicSharedMemorySize, HG_SMEM);
    cudaFuncSetAttribute(prep_hgemm,
                         cudaFuncAttributeMaxDynamicSharedMemorySize, HG_SMEM);

    // 1) ALL small prep work: gf->fp16, W converts, Wf transpose, c0/c/S
    prep_misc<<<8834, 256>>>(gf, Wq, Wk, Wv, Wf, wdr, bdr, bq, bv, bfv,
                             gfh, Wqh, Wkh, Wvh, WfTh, c0, c, S);
    // 2) all three weight products (fp16 HMMA pipeline, one wave)
    prep_hgemm<<<dim3(4, 4, 3), 256, HG_SMEM>>>(Wkh, Wqh, WfTh, Wvh, S, M0h, MMh);
    // 3) t = gf_h @ M0 + c0 -> fp16   [B,512], K=512
    hgemm<16, false, false, true><<<dim3(FDIM / 128, BATCH / 128), 256, HG_SMEM>>>(
        gfh, nullptr, M0h, FDIM, c0, nullptr, nullptr, th);
    // 4) row kernel: softmax weights, u (fp16), res (fp16) = lf_mean + b_dr
    row_fused_kernel<<<BATCH, 128>>>(
        (const float4*)lf, (const uint2*)th, wdr, bdr, (uint2*)uh, (uint2*)resh);
    // 5) out = relu([u|gf] @ MM + c) + res + gf   [B,512], K=1024
    hgemm<32, true, true, false><<<dim3(FDIM / 128, BATCH / 128), 256, HG_SMEM>>>(
        uh, gfh, MMh, 2 * FDIM, c, resh, gf, out);
}